// round 16
// baseline (speedup 1.0000x reference)
#include <cuda_runtime.h>
#include <cuda_fp16.h>

// Problem constants (fixed by the dataset)
#define NN 100000
#define CC 48
#define EE 1600000
#define MM 20000
#define LL 10
#define LAMF 0.9f
#define OMLAMF 0.1f

#define XSTRIDE 64   // halves per x-row (128B padded) -> gathers hit one cache line

#define SCAN_BLOCK 1024
#define SCAN_ITEMS 4
#define SCAN_TILE  (SCAN_BLOCK * SCAN_ITEMS)            // 4096
#define NTILES     ((NN + SCAN_TILE - 1) / SCAN_TILE)   // 25

// padded edge capacity: rows padded to even count; +6 slack for depth-2 overread
#define PADE  (EE + NN + 6)

// ---------------- device scratch (no allocations allowed) ----------------
__device__ int    d_deg[NN];
__device__ float  d_dinv[NN];
__device__ int    d_rowcnt[NN];       // true out-count per row
__device__ int4   d_rowmeta[NN];      // {rowptr, rowcnt, s=LAM*dinv[r], 1/s}
__device__ int    d_cursor[NN];
__device__ int    d_winner[NN];       // last mask index targeting node (-1)
__device__ int2   d_edges[PADE];      // {col, dinv[col]}; pads {0,0}
__device__ __half d_G01h[NN * CC];    // 0.1*G  (fp16)
__device__ __half d_xA[NN * XSTRIDE]; // fp16 ping (128B row stride)
__device__ __half d_xB[NN * XSTRIDE]; // fp16 pong (holds x0)
__device__ int    d_tileSum[NTILES];

__device__ __forceinline__ int padded(int c) { return (c + 1) & ~1; }

// ---------------- preprocessing ----------------
// 2 edges per thread (int2 loads); winner selection fused; first threads write
// the prefetch slack slots. (R13-measured best shape.)
__global__ void k_count(const int2* __restrict__ row2, const int2* __restrict__ col2,
                        const int* __restrict__ mask) {
    int e = blockIdx.x * blockDim.x + threadIdx.x;
    if (e < 6) d_edges[EE + NN + e] = make_int2(0, 0);   // prefetch slack
    if (e < EE / 2) {
        int2 r = __ldg(row2 + e);
        int2 c = __ldg(col2 + e);
        atomicAdd(&d_rowcnt[r.x], 1);
        atomicAdd(&d_rowcnt[r.y], 1);
        atomicAdd(&d_deg[c.x], 1);
        atomicAdd(&d_deg[c.y], 1);
    }
    if (e < MM) atomicMax(&d_winner[mask[e]], e);
}

__global__ void k_scan_reduce() {
    __shared__ int sdata[SCAN_BLOCK];
    int t = threadIdx.x, b = blockIdx.x;
    int base = b * SCAN_TILE;
    int s = 0;
#pragma unroll
    for (int i = 0; i < SCAN_ITEMS; i++) {
        int idx = base + t + i * SCAN_BLOCK;
        if (idx < NN) {
            s += padded(d_rowcnt[idx]);
            d_dinv[idx] = rsqrtf((float)d_deg[idx]);   // deg >= 1 guaranteed
        }
    }
    sdata[t] = s;
    __syncthreads();
    for (int o = SCAN_BLOCK / 2; o > 0; o >>= 1) {
        if (t < o) sdata[t] += sdata[t + o];
        __syncthreads();
    }
    if (t == 0) d_tileSum[b] = sdata[0];
}

// final scan: two-level shfl warp scan; writes int4 rowmeta {ptr,cnt,s,1/s},
// cursor, and the {0,0} pad slot for odd-count rows.
__global__ void k_scan_final() {
    __shared__ int s_warpSum[32];
    __shared__ int s_tileOff;
    int t = threadIdx.x, b = blockIdx.x;
    int lane = t & 31, wid = t >> 5;
    int base = b * SCAN_TILE;

    int tc[SCAN_ITEMS], v[SCAN_ITEMS];
    int s = 0;
#pragma unroll
    for (int i = 0; i < SCAN_ITEMS; i++) {
        int idx = base + t * SCAN_ITEMS + i;
        tc[i] = (idx < NN) ? d_rowcnt[idx] : 0;
        v[i] = (idx < NN) ? padded(tc[i]) : 0;
        s += v[i];
    }

    int incl = s;
#pragma unroll
    for (int o = 1; o < 32; o <<= 1) {
        int u = __shfl_up_sync(0xffffffff, incl, o);
        if (lane >= o) incl += u;
    }
    if (lane == 31) s_warpSum[wid] = incl;
    __syncthreads();

    if (wid == 0) {
        int wv = s_warpSum[lane];
        int wi = wv;
#pragma unroll
        for (int o = 1; o < 32; o <<= 1) {
            int u = __shfl_up_sync(0xffffffff, wi, o);
            if (lane >= o) wi += u;
        }
        s_warpSum[lane] = wi - wv;   // exclusive warp offset
    } else if (wid == 1) {
        int tv = (lane < NTILES) ? d_tileSum[lane] : 0;
        int ti = tv;
#pragma unroll
        for (int o = 1; o < 32; o <<= 1) {
            int u = __shfl_up_sync(0xffffffff, ti, o);
            if (lane >= o) ti += u;
        }
        if (lane == b) s_tileOff = ti - tv;
    }
    __syncthreads();

    int run = (incl - s) + s_warpSum[wid] + s_tileOff;
#pragma unroll
    for (int i = 0; i < SCAN_ITEMS; i++) {
        int idx = base + t * SCAN_ITEMS + i;
        if (idx < NN) {
            float sf = LAMF * d_dinv[idx];
            float si = 1.0f / sf;
            d_rowmeta[idx] = make_int4(run, tc[i],
                                       __float_as_int(sf), __float_as_int(si));
            d_cursor[idx] = run;
            if (tc[i] & 1)
                d_edges[run + tc[i]] = make_int2(0, 0);   // pad slot w=0
            run += v[i];
        }
    }
}

// edge fill: 2 edges per thread; stores {col, dinv[col]} — the per-row factor
// LAM*dinv[row] is applied in the spmm epilogue (weight factorization), so the
// dinv[row] random gather is eliminated here (3 random sector ops/edge, was 4).
__global__ void k_fill(const int2* __restrict__ row2, const int2* __restrict__ col2) {
    int e = blockIdx.x * blockDim.x + threadIdx.x;
    if (e < EE / 2) {
        int2 r = __ldg(row2 + e);
        int2 c = __ldg(col2 + e);
        float dc0 = d_dinv[c.x];
        float dc1 = d_dinv[c.y];
        int p0 = atomicAdd(&d_cursor[r.x], 1);
        d_edges[p0] = make_int2(c.x, __float_as_int(dc0));
        int p1 = atomicAdd(&d_cursor[r.y], 1);
        d_edges[p1] = make_int2(c.y, __float_as_int(dc1));
    }
}

// G build, vectorized: thread = 4 contiguous channels of one node.
__global__ void k_buildG(const float* __restrict__ Z, const float* __restrict__ Y) {
    int idx = blockIdx.x * blockDim.x + threadIdx.x;   // 0 .. NN*12-1
    if (idx >= NN * (CC / 4)) return;
    int n = idx / (CC / 4);
    int c4 = (idx % (CC / 4)) * 4;
    int wi = d_winner[n];
    const float* src = (wi >= 0) ? (Y + (size_t)wi * CC) : (Z + (size_t)n * CC);
    float4 g = *(const float4*)(src + c4);

    __half2 x0a = __floats2half2_rn(g.x, g.y);
    __half2 x0b = __floats2half2_rn(g.z, g.w);
    uint2 xs;
    xs.x = *reinterpret_cast<unsigned*>(&x0a);
    xs.y = *reinterpret_cast<unsigned*>(&x0b);
    *(uint2*)(d_xB + (size_t)n * XSTRIDE + c4) = xs;

    __half2 ga = __floats2half2_rn(OMLAMF * g.x, OMLAMF * g.y);
    __half2 gb = __floats2half2_rn(OMLAMF * g.z, OMLAMF * g.w);
    uint2 gs;
    gs.x = *reinterpret_cast<unsigned*>(&ga);
    gs.y = *reinterpret_cast<unsigned*>(&gb);
    *(uint2*)(d_G01h + (size_t)n * CC + c4) = gs;
}

// ---------------- SpMM: warp-per-row, depth-2 pipeline ------------------------
// Hot loop identical to the protected R10 structure. Weight factorization:
// edges carry dinv[col]; acc is seeded with g01*(1/s) and scaled by s=LAM*dinv[r]
// after the shuffle merge, giving s*sum(dinv[c]*x[c]) + 0.1*G exactly.
template <bool FINAL>
__global__ __launch_bounds__(256, 8) void k_spmm(const __half* __restrict__ x,
                                                 void* __restrict__ outp) {
    int gw = (blockIdx.x * blockDim.x + threadIdx.x) >> 5;
    if (gw >= NN) return;
    const int lane = threadIdx.x & 31;
    const int half = lane >> 4;
    const int sub = lane & 15;
    const bool active = sub < 12;
    const unsigned bofs = sub * 8;   // byte offset of this lane's uint2 in a row

    const int4 meta = __ldg(&d_rowmeta[gw]);      // {ptr, cnt, s, 1/s}
    const int np = (meta.y + 1) >> 1;             // pair count
    const float srow = __int_as_float(meta.z);
    const float sinv = __int_as_float(meta.w);
    const int2* ep2 = d_edges + meta.x + half;    // this half's stream
    const char* xb = (const char*)x;

    // prologue: edges 0,1 + gather 0 + scaled G preload (half 0 only)
    int2 e0 = __ldg(ep2);
    int2 e1 = __ldg(ep2 + 2);
    uint2 r0 = make_uint2(0u, 0u);
    if (active) r0 = __ldg((const uint2*)(xb + (((unsigned)e0.x) << 7) + bofs));
    float w0 = __int_as_float(e0.y);

    float4 acc = make_float4(0.f, 0.f, 0.f, 0.f);
    const unsigned go = (unsigned)gw * CC + sub * 4;
    if (half == 0 && active) {
        uint2 graw = __ldg((const uint2*)(d_G01h + go));
        __half2 g0, g1;
        *reinterpret_cast<unsigned*>(&g0) = graw.x;
        *reinterpret_cast<unsigned*>(&g1) = graw.y;
        float2 gf0 = __half22float2(g0);
        float2 gf1 = __half22float2(g1);
        acc = make_float4(gf0.x * sinv, gf0.y * sinv, gf1.x * sinv, gf1.y * sinv);
    }

    for (int j = 0; j < np; j++) {
        int2 e2 = __ldg(ep2 + 2 * (j + 2));   // unconditional; slack-covered
        uint2 r1 = make_uint2(0u, 0u);
        if (active) r1 = __ldg((const uint2*)(xb + (((unsigned)e1.x) << 7) + bofs));
        float w1 = __int_as_float(e1.y);
        if (active) {
            __half2 h0, h1;
            *reinterpret_cast<unsigned*>(&h0) = r0.x;
            *reinterpret_cast<unsigned*>(&h1) = r0.y;
            float2 f0 = __half22float2(h0);
            float2 f1 = __half22float2(h1);
            acc.x = fmaf(w0, f0.x, acc.x);
            acc.y = fmaf(w0, f0.y, acc.y);
            acc.z = fmaf(w0, f1.x, acc.z);
            acc.w = fmaf(w0, f1.y, acc.w);
        }
        e1 = e2;
        r0 = r1;
        w0 = w1;
    }

    acc.x += __shfl_xor_sync(0xffffffff, acc.x, 16);
    acc.y += __shfl_xor_sync(0xffffffff, acc.y, 16);
    acc.z += __shfl_xor_sync(0xffffffff, acc.z, 16);
    acc.w += __shfl_xor_sync(0xffffffff, acc.w, 16);

    if (half == 0 && active) {
        acc.x *= srow;
        acc.y *= srow;
        acc.z *= srow;
        acc.w *= srow;
        if (FINAL) {
            *(float4*)((float*)outp + go) = acc;
        } else {
            __half2 o0 = __floats2half2_rn(acc.x, acc.y);
            __half2 o1 = __floats2half2_rn(acc.z, acc.w);
            uint2 st;
            st.x = *reinterpret_cast<unsigned*>(&o0);
            st.y = *reinterpret_cast<unsigned*>(&o1);
            *(uint2*)((char*)outp + ((unsigned)gw << 7) + bofs) = st;
        }
    }
}

// ---------------- launch ----------------
extern "C" void kernel_launch(void* const* d_in, const int* in_sizes, int n_in,
                              void* d_out, int out_size) {
    const float* Z = (const float*)d_in[0];
    const float* Y = (const float*)d_in[1];
    const int* mask = (const int*)d_in[2];
    const int* ei = (const int*)d_in[3];   // [2, E]: row then col
    const int* row = ei;
    const int* col = ei + EE;

    __half *xA, *xB;
    cudaGetSymbolAddress((void**)&xA, d_xA);
    cudaGetSymbolAddress((void**)&xB, d_xB);
    int *degp, *cntp, *winp;
    cudaGetSymbolAddress((void**)&degp, d_deg);
    cudaGetSymbolAddress((void**)&cntp, d_rowcnt);
    cudaGetSymbolAddress((void**)&winp, d_winner);

    cudaMemsetAsync(degp, 0, NN * sizeof(int));
    cudaMemsetAsync(cntp, 0, NN * sizeof(int));
    cudaMemsetAsync(winp, 0xFF, NN * sizeof(int));   // -1

    const int tb = 256;
    k_count<<<(EE / 2 + tb - 1) / tb, tb>>>((const int2*)row, (const int2*)col, mask);
    k_scan_reduce<<<NTILES, SCAN_BLOCK>>>();
    k_scan_final<<<NTILES, SCAN_BLOCK>>>();
    k_fill<<<(EE / 2 + tb - 1) / tb, tb>>>((const int2*)row, (const int2*)col);
    k_buildG<<<(NN * (CC / 4) + tb - 1) / tb, tb>>>(Z, Y);

    const int spmm_blocks = (NN * 32 + tb - 1) / tb;
    const __half* cur = xB;                  // x0
    for (int it = 0; it < LL - 1; ++it) {
        __half* nxt = (it & 1) ? xB : xA;
        k_spmm<false><<<spmm_blocks, tb>>>(cur, nxt);
        cur = nxt;
    }
    k_spmm<true><<<spmm_blocks, tb>>>(cur, d_out);
}

// round 17
// speedup vs baseline: 1.0666x; 1.0666x over previous
#include <cuda_runtime.h>
#include <cuda_fp16.h>

// Problem constants (fixed by the dataset)
#define NN 100000
#define CC 48
#define EE 1600000
#define MM 20000
#define LL 10
#define LAMF 0.9f
#define OMLAMF 0.1f

#define XSTRIDE 64   // halves per x-row (128B padded) -> gathers hit one cache line

#define SCAN_BLOCK 1024
#define SCAN_ITEMS 4
#define SCAN_TILE  (SCAN_BLOCK * SCAN_ITEMS)            // 4096
#define NTILES     ((NN + SCAN_TILE - 1) / SCAN_TILE)   // 25

// padded edge capacity: rows padded to even count; +6 slack for depth-2 overread
#define PADE  (EE + NN + 6)

#define TB 256
#define FILL_BLOCKS   ((EE / 2 + TB - 1) / TB)            // 3125
#define BUILDG_BLOCKS ((NN * (CC / 4) + TB - 1) / TB)     // 4688

// ---------------- device scratch (no allocations allowed) ----------------
__device__ int    d_deg[NN];
__device__ float  d_dinv[NN];
__device__ int    d_rowcnt[NN];       // true out-count per row
__device__ int2   d_rowmeta[NN];      // {rowptr (padded int2 space), rowcnt}
__device__ int    d_cursor[NN];
__device__ int    d_winner[NN];       // last mask index targeting node (-1)
__device__ int2   d_edges[PADE];      // {col, w}; w prescaled by LAM; pads w=0
__device__ __half d_G01h[NN * CC];    // 0.1*G  (fp16)
__device__ __half d_xA[NN * XSTRIDE]; // fp16 ping (128B row stride)
__device__ __half d_xB[NN * XSTRIDE]; // fp16 pong (holds x0)
__device__ int    d_tileSum[NTILES];

__device__ __forceinline__ int padded(int c) { return (c + 1) & ~1; }

// ---------------- preprocessing ----------------
// 2 edges per thread (int2 loads); winner selection fused; first threads write
// the prefetch slack slots. (R13-measured best shape.)
__global__ void k_count(const int2* __restrict__ row2, const int2* __restrict__ col2,
                        const int* __restrict__ mask) {
    int e = blockIdx.x * blockDim.x + threadIdx.x;
    if (e < 6) d_edges[EE + NN + e] = make_int2(0, 0);   // prefetch slack
    if (e < EE / 2) {
        int2 r = __ldg(row2 + e);
        int2 c = __ldg(col2 + e);
        atomicAdd(&d_rowcnt[r.x], 1);
        atomicAdd(&d_rowcnt[r.y], 1);
        atomicAdd(&d_deg[c.x], 1);
        atomicAdd(&d_deg[c.y], 1);
    }
    if (e < MM) atomicMax(&d_winner[mask[e]], e);
}

__global__ void k_scan_reduce() {
    __shared__ int sdata[SCAN_BLOCK];
    int t = threadIdx.x, b = blockIdx.x;
    int base = b * SCAN_TILE;
    int s = 0;
#pragma unroll
    for (int i = 0; i < SCAN_ITEMS; i++) {
        int idx = base + t + i * SCAN_BLOCK;
        if (idx < NN) {
            s += padded(d_rowcnt[idx]);
            d_dinv[idx] = rsqrtf((float)d_deg[idx]);   // deg >= 1 guaranteed
        }
    }
    sdata[t] = s;
    __syncthreads();
    for (int o = SCAN_BLOCK / 2; o > 0; o >>= 1) {
        if (t < o) sdata[t] += sdata[t + o];
        __syncthreads();
    }
    if (t == 0) d_tileSum[b] = sdata[0];
}

// final scan: two-level shfl warp scan (2 barriers total). Warp 1 scans the
// 25 tile sums for this block's global offset.
__global__ void k_scan_final() {
    __shared__ int s_warpSum[32];
    __shared__ int s_tileOff;
    int t = threadIdx.x, b = blockIdx.x;
    int lane = t & 31, wid = t >> 5;
    int base = b * SCAN_TILE;

    int tc[SCAN_ITEMS], v[SCAN_ITEMS];
    int s = 0;
#pragma unroll
    for (int i = 0; i < SCAN_ITEMS; i++) {
        int idx = base + t * SCAN_ITEMS + i;
        tc[i] = (idx < NN) ? d_rowcnt[idx] : 0;
        v[i] = (idx < NN) ? padded(tc[i]) : 0;
        s += v[i];
    }

    int incl = s;
#pragma unroll
    for (int o = 1; o < 32; o <<= 1) {
        int u = __shfl_up_sync(0xffffffff, incl, o);
        if (lane >= o) incl += u;
    }
    if (lane == 31) s_warpSum[wid] = incl;
    __syncthreads();

    if (wid == 0) {
        int wv = s_warpSum[lane];
        int wi = wv;
#pragma unroll
        for (int o = 1; o < 32; o <<= 1) {
            int u = __shfl_up_sync(0xffffffff, wi, o);
            if (lane >= o) wi += u;
        }
        s_warpSum[lane] = wi - wv;   // exclusive warp offset
    } else if (wid == 1) {
        int tv = (lane < NTILES) ? d_tileSum[lane] : 0;
        int ti = tv;
#pragma unroll
        for (int o = 1; o < 32; o <<= 1) {
            int u = __shfl_up_sync(0xffffffff, ti, o);
            if (lane >= o) ti += u;
        }
        if (lane == b) s_tileOff = ti - tv;
    }
    __syncthreads();

    int run = (incl - s) + s_warpSum[wid] + s_tileOff;
#pragma unroll
    for (int i = 0; i < SCAN_ITEMS; i++) {
        int idx = base + t * SCAN_ITEMS + i;
        if (idx < NN) {
            d_rowmeta[idx] = make_int2(run, tc[i]);
            d_cursor[idx] = run;
            if (tc[i] & 1)
                d_edges[run + tc[i]] = make_int2(0, 0);   // pad slot w=0
            run += v[i];
        }
    }
}

// FUSED fill + buildG: blockIdx partitions the work. Fill blocks are LSU-
// latency-bound (issue ~3%), buildG blocks are streaming — co-residency lets
// buildG hide inside fill's stall slots and saves a launch.
__global__ void k_fill_G(const int2* __restrict__ row2, const int2* __restrict__ col2,
                         const float* __restrict__ Z, const float* __restrict__ Y) {
    if (blockIdx.x < FILL_BLOCKS) {
        int e = blockIdx.x * TB + threadIdx.x;
        if (e < EE / 2) {
            int2 r = __ldg(row2 + e);
            int2 c = __ldg(col2 + e);
            float w0 = LAMF * d_dinv[r.x] * d_dinv[c.x];
            float w1 = LAMF * d_dinv[r.y] * d_dinv[c.y];
            int p0 = atomicAdd(&d_cursor[r.x], 1);
            d_edges[p0] = make_int2(c.x, __float_as_int(w0));
            int p1 = atomicAdd(&d_cursor[r.y], 1);
            d_edges[p1] = make_int2(c.y, __float_as_int(w1));
        }
    } else {
        int idx = (blockIdx.x - FILL_BLOCKS) * TB + threadIdx.x;  // 0 .. NN*12-1
        if (idx >= NN * (CC / 4)) return;
        int n = idx / (CC / 4);
        int c4 = (idx % (CC / 4)) * 4;
        int wi = d_winner[n];
        const float* src = (wi >= 0) ? (Y + (size_t)wi * CC) : (Z + (size_t)n * CC);
        float4 g = *(const float4*)(src + c4);

        __half2 x0a = __floats2half2_rn(g.x, g.y);
        __half2 x0b = __floats2half2_rn(g.z, g.w);
        uint2 xs;
        xs.x = *reinterpret_cast<unsigned*>(&x0a);
        xs.y = *reinterpret_cast<unsigned*>(&x0b);
        *(uint2*)(d_xB + (size_t)n * XSTRIDE + c4) = xs;

        __half2 ga = __floats2half2_rn(OMLAMF * g.x, OMLAMF * g.y);
        __half2 gb = __floats2half2_rn(OMLAMF * g.z, OMLAMF * g.w);
        uint2 gs;
        gs.x = *reinterpret_cast<unsigned*>(&ga);
        gs.y = *reinterpret_cast<unsigned*>(&gb);
        *(uint2*)(d_G01h + (size_t)n * CC + c4) = gs;
    }
}

// ---------------- SpMM: warp-per-row, depth-2 pipeline, G-preloaded acc -------
// PROTECTED local optimum (R10/R13 structure, byte-identical — do not touch).
template <bool FINAL>
__global__ __launch_bounds__(256, 8) void k_spmm(const __half* __restrict__ x,
                                                 void* __restrict__ outp) {
    int gw = (blockIdx.x * blockDim.x + threadIdx.x) >> 5;
    if (gw >= NN) return;
    const int lane = threadIdx.x & 31;
    const int half = lane >> 4;
    const int sub = lane & 15;
    const bool active = sub < 12;
    const unsigned bofs = sub * 8;   // byte offset of this lane's uint2 in a row

    const int2 meta = __ldg(&d_rowmeta[gw]);                // {ptr, cnt}
    const int np = (meta.y + 1) >> 1;                       // pair count
    const int2* ep2 = d_edges + meta.x + half;              // this half's stream
    const char* xb = (const char*)x;

    // prologue: edges 0,1 + gather 0 + G preload (half 0 only)
    int2 e0 = __ldg(ep2);
    int2 e1 = __ldg(ep2 + 2);
    uint2 r0 = make_uint2(0u, 0u);
    if (active) r0 = __ldg((const uint2*)(xb + (((unsigned)e0.x) << 7) + bofs));
    float w0 = __int_as_float(e0.y);

    float4 acc = make_float4(0.f, 0.f, 0.f, 0.f);
    const unsigned go = (unsigned)gw * CC + sub * 4;
    if (half == 0 && active) {
        uint2 graw = __ldg((const uint2*)(d_G01h + go));
        __half2 g0, g1;
        *reinterpret_cast<unsigned*>(&g0) = graw.x;
        *reinterpret_cast<unsigned*>(&g1) = graw.y;
        float2 gf0 = __half22float2(g0);
        float2 gf1 = __half22float2(g1);
        acc = make_float4(gf0.x, gf0.y, gf1.x, gf1.y);
    }

    for (int j = 0; j < np; j++) {
        int2 e2 = __ldg(ep2 + 2 * (j + 2));   // unconditional; slack-covered
        uint2 r1 = make_uint2(0u, 0u);
        if (active) r1 = __ldg((const uint2*)(xb + (((unsigned)e1.x) << 7) + bofs));
        float w1 = __int_as_float(e1.y);
        if (active) {
            __half2 h0, h1;
            *reinterpret_cast<unsigned*>(&h0) = r0.x;
            *reinterpret_cast<unsigned*>(&h1) = r0.y;
            float2 f0 = __half22float2(h0);
            float2 f1 = __half22float2(h1);
            acc.x = fmaf(w0, f0.x, acc.x);
            acc.y = fmaf(w0, f0.y, acc.y);
            acc.z = fmaf(w0, f1.x, acc.z);
            acc.w = fmaf(w0, f1.y, acc.w);
        }
        e1 = e2;
        r0 = r1;
        w0 = w1;
    }

    acc.x += __shfl_xor_sync(0xffffffff, acc.x, 16);
    acc.y += __shfl_xor_sync(0xffffffff, acc.y, 16);
    acc.z += __shfl_xor_sync(0xffffffff, acc.z, 16);
    acc.w += __shfl_xor_sync(0xffffffff, acc.w, 16);

    if (half == 0 && active) {
        if (FINAL) {
            *(float4*)((float*)outp + go) = acc;
        } else {
            __half2 o0 = __floats2half2_rn(acc.x, acc.y);
            __half2 o1 = __floats2half2_rn(acc.z, acc.w);
            uint2 st;
            st.x = *reinterpret_cast<unsigned*>(&o0);
            st.y = *reinterpret_cast<unsigned*>(&o1);
            *(uint2*)((char*)outp + ((unsigned)gw << 7) + bofs) = st;
        }
    }
}

// ---------------- launch ----------------
extern "C" void kernel_launch(void* const* d_in, const int* in_sizes, int n_in,
                              void* d_out, int out_size) {
    const float* Z = (const float*)d_in[0];
    const float* Y = (const float*)d_in[1];
    const int* mask = (const int*)d_in[2];
    const int* ei = (const int*)d_in[3];   // [2, E]: row then col
    const int* row = ei;
    const int* col = ei + EE;

    __half *xA, *xB;
    cudaGetSymbolAddress((void**)&xA, d_xA);
    cudaGetSymbolAddress((void**)&xB, d_xB);
    int *degp, *cntp, *winp;
    cudaGetSymbolAddress((void**)&degp, d_deg);
    cudaGetSymbolAddress((void**)&cntp, d_rowcnt);
    cudaGetSymbolAddress((void**)&winp, d_winner);

    cudaMemsetAsync(degp, 0, NN * sizeof(int));
    cudaMemsetAsync(cntp, 0, NN * sizeof(int));
    cudaMemsetAsync(winp, 0xFF, NN * sizeof(int));   // -1

    k_count<<<(EE / 2 + TB - 1) / TB, TB>>>((const int2*)row, (const int2*)col, mask);
    k_scan_reduce<<<NTILES, SCAN_BLOCK>>>();
    k_scan_final<<<NTILES, SCAN_BLOCK>>>();
    k_fill_G<<<FILL_BLOCKS + BUILDG_BLOCKS, TB>>>((const int2*)row, (const int2*)col, Z, Y);

    const int spmm_blocks = (NN * 32 + TB - 1) / TB;
    const __half* cur = xB;                  // x0
    for (int it = 0; it < LL - 1; ++it) {
        __half* nxt = (it & 1) ? xB : xA;
        k_spmm<false><<<spmm_blocks, TB>>>(cur, nxt);
        cur = nxt;
    }
    k_spmm<true><<<spmm_blocks, TB>>>(cur, d_out);
}